// round 2
// baseline (speedup 1.0000x reference)
#include <cuda_runtime.h>

// Problem constants (fixed shapes from reference):
//   x:      (16, 256, 64, 64)  fp32
//   weight: (8, 256)           fp32   (2*scale^2 offset channels, scale=2)
//   bias:   (8,)               fp32
//   out:    (16, 256, 128, 128) fp32
#define Bn  16
#define Cn  256
#define Hn  64
#define Wn  64
#define OYn 128
#define OXn 128

// Per-output-pixel sampling coordinates (ix, iy). 16*128*128 float2 = 2 MB.
__device__ float2 g_coord[Bn * OYn * OXn];

// ---------------------------------------------------------------------------
// Stage 1: 1x1 conv (8 dots of length 256 per input pixel) + pixel shuffle +
// grid construction. One thread per input pixel (b, h, w); each thread emits
// coords for its 4 output pixels (2x2 shuffle block).
// ---------------------------------------------------------------------------
__global__ void dysample_stage1(const float* __restrict__ x,
                                const float* __restrict__ weight,
                                const float* __restrict__ bias)
{
    // Transposed weight in SMEM: wt[c*8 + o] so the 8 per-channel weights are
    // two contiguous float4 loads per c (2x LDS.128 instead of 8x LDS.32).
    __shared__ float wt[Cn * 8];
    for (int i = threadIdx.x; i < Cn * 8; i += blockDim.x) {
        int o = i >> 8;       // 0..7
        int c = i & 255;      // 0..255
        wt[c * 8 + o] = weight[i];
    }
    __syncthreads();

    int tid = blockIdx.x * blockDim.x + threadIdx.x;   // 0 .. 65535
    int w = tid & 63;
    int h = (tid >> 6) & 63;
    int b = tid >> 12;

    const float* xb = x + (size_t)b * Cn * Hn * Wn + h * Wn + w;

    float acc[8];
#pragma unroll
    for (int s = 0; s < 8; s++) acc[s] = 0.0f;

#pragma unroll 4
    for (int c = 0; c < Cn; c++) {
        float xv = __ldg(xb + (size_t)c * Hn * Wn);    // coalesced along w
        float4 wa = *reinterpret_cast<const float4*>(wt + c * 8);
        float4 wb = *reinterpret_cast<const float4*>(wt + c * 8 + 4);
        acc[0] = fmaf(xv, wa.x, acc[0]);
        acc[1] = fmaf(xv, wa.y, acc[1]);
        acc[2] = fmaf(xv, wa.z, acc[2]);
        acc[3] = fmaf(xv, wa.w, acc[3]);
        acc[4] = fmaf(xv, wb.x, acc[4]);
        acc[5] = fmaf(xv, wb.y, acc[5]);
        acc[6] = fmaf(xv, wb.z, acc[6]);
        acc[7] = fmaf(xv, wb.w, acc[7]);
    }

    // Pixel shuffle: output (oy=2h+r1, ox=2w+r2) uses offset channels
    // s = r1*2 + r2 (x-coord channel) and 4+s (y-coord channel).
    // Reference quirk reproduced: grid[...,0] (x-coord) = h-linspace(oy),
    // grid[...,1] (y-coord) = w-linspace(ox).
#pragma unroll
    for (int s = 0; s < 4; s++) {
        int r1 = s >> 1;
        int r2 = s & 1;
        int oy = 2 * h + r1;
        int ox = 2 * w + r2;
        float gx = fmaf((float)oy, 2.0f / 127.0f, -1.0f) + acc[s]     + __ldg(&bias[s]);
        float gy = fmaf((float)ox, 2.0f / 127.0f, -1.0f) + acc[4 + s] + __ldg(&bias[4 + s]);
        // ix = ((gx+1)*W - 1)*0.5 with W=64  ->  32*gx + 31.5
        float ix = fmaf(gx, 32.0f, 31.5f);
        float iy = fmaf(gy, 32.0f, 31.5f);
        g_coord[(b * OYn + oy) * OXn + ox] = make_float2(ix, iy);
    }
}

// ---------------------------------------------------------------------------
// Stage 2: bilinear sample with zeros padding. One thread per
// (b, 4-channel group, oy, ox): coords + corner weights computed once,
// reused across 4 channels (same spatial corners, different planes).
// ---------------------------------------------------------------------------
__global__ void dysample_stage2(const float* __restrict__ x,
                                float* __restrict__ out)
{
    int idx = blockIdx.x * blockDim.x + threadIdx.x;   // 0 .. 16M-1
    int ox = idx & 127;
    int oy = (idx >> 7) & 127;
    int c4 = (idx >> 14) & 63;   // channel group (4 channels each)
    int b  = idx >> 20;          // 0..15

    float2 co = g_coord[(b * OYn + oy) * OXn + ox];
    float fx = floorf(co.x);
    float fy = floorf(co.y);
    int x0 = (int)fx;
    int y0 = (int)fy;
    float wx = co.x - fx;
    float wy = co.y - fy;

    float w00 = (1.0f - wy) * (1.0f - wx);
    float w01 = (1.0f - wy) * wx;
    float w10 = wy * (1.0f - wx);
    float w11 = wy * wx;

    // zeros padding == zero the weight of out-of-bounds corners, clamp index
    if ((unsigned)x0       >= (unsigned)Wn) { w00 = 0.0f; w10 = 0.0f; }
    if ((unsigned)(x0 + 1) >= (unsigned)Wn) { w01 = 0.0f; w11 = 0.0f; }
    if ((unsigned)y0       >= (unsigned)Hn) { w00 = 0.0f; w01 = 0.0f; }
    if ((unsigned)(y0 + 1) >= (unsigned)Hn) { w10 = 0.0f; w11 = 0.0f; }

    int xc0 = min(max(x0, 0), Wn - 1);
    int xc1 = min(max(x0 + 1, 0), Wn - 1);
    int yc0 = min(max(y0, 0), Hn - 1);
    int yc1 = min(max(y0 + 1, 0), Hn - 1);

    int o00 = yc0 * Wn + xc0;
    int o01 = yc0 * Wn + xc1;
    int o10 = yc1 * Wn + xc0;
    int o11 = yc1 * Wn + xc1;

    const float* xp = x + ((size_t)b * Cn + (size_t)c4 * 4) * (Hn * Wn);
    float* op = out + ((size_t)b * Cn + (size_t)c4 * 4) * ((size_t)OYn * OXn)
                    + (size_t)oy * OXn + ox;

#pragma unroll
    for (int k = 0; k < 4; k++) {
        const float* q = xp + (size_t)k * (Hn * Wn);
        float v = fmaf(__ldg(q + o00), w00,
                  fmaf(__ldg(q + o01), w01,
                  fmaf(__ldg(q + o10), w10,
                       __ldg(q + o11) * w11)));
        op[(size_t)k * (OYn * OXn)] = v;
    }
}

extern "C" void kernel_launch(void* const* d_in, const int* in_sizes, int n_in,
                              void* d_out, int out_size)
{
    const float* x      = (const float*)d_in[0];
    const float* weight = (const float*)d_in[1];
    const float* bias   = (const float*)d_in[2];
    float* out          = (float*)d_out;

    // Stage 1: 16*64*64 = 65536 threads
    dysample_stage1<<<256, 256>>>(x, weight, bias);

    // Stage 2: 16 * 64 groups * 128 * 128 = 16,777,216 threads
    dysample_stage2<<<65536, 256>>>(x, out);
}

// round 3
// speedup vs baseline: 2.1159x; 2.1159x over previous
#include <cuda_runtime.h>

// Problem constants (fixed shapes):
//   x:      (16, 256, 64, 64)  fp32
//   weight: (8, 256)           fp32
//   bias:   (8,)               fp32
//   out:    (16, 256, 128, 128) fp32
#define Bn  16
#define Cn  256
#define Hn  64
#define Wn  64
#define OYn 128
#define OXn 128
#define PLANE (Hn * Wn)        // 4096
#define PADW 65                // padded row stride (float2 elements)

// Per-output-pixel sampling coordinates (ix, iy). 16*128*128 float2 = 2 MB.
__device__ float2 g_coord[Bn * OYn * OXn];

// ---------------------------------------------------------------------------
// Stage 1: 1x1 conv (8 dots of length 256) + pixel shuffle + grid build.
// Block = one (b, h) row: 64 pixels x 4 channel-parts (64 ch each).
// 4-way split shortens the dependent-load chain; SMEM reduce combines.
// ---------------------------------------------------------------------------
__global__ __launch_bounds__(256) void dysample_stage1(
    const float* __restrict__ x,
    const float* __restrict__ weight,
    const float* __restrict__ bias)
{
    __shared__ float wt[Cn * 8];          // transposed: wt[c*8+o]
    __shared__ float part[3][64][9];      // padded to 9 -> conflict-free

    for (int i = threadIdx.x; i < Cn * 8; i += 256)
        wt[(i & 255) * 8 + (i >> 8)] = weight[i];
    __syncthreads();

    int w     = threadIdx.x & 63;
    int cpart = threadIdx.x >> 6;         // 0..3
    int bh    = blockIdx.x;               // b*64 + h
    int b     = bh >> 6;
    int h     = bh & 63;

    const float* xb = x + ((size_t)b * Cn + cpart * 64) * PLANE + h * Wn + w;
    const float* wr0 = &wt[(cpart * 64) * 8];

    float acc[8];
#pragma unroll
    for (int s = 0; s < 8; s++) acc[s] = 0.0f;

#pragma unroll 8
    for (int c = 0; c < 64; ++c) {
        float xv = __ldg(xb + (size_t)c * PLANE);       // coalesced along w
        float4 wa = *reinterpret_cast<const float4*>(wr0 + c * 8);
        float4 wb = *reinterpret_cast<const float4*>(wr0 + c * 8 + 4);
        acc[0] = fmaf(xv, wa.x, acc[0]);
        acc[1] = fmaf(xv, wa.y, acc[1]);
        acc[2] = fmaf(xv, wa.z, acc[2]);
        acc[3] = fmaf(xv, wa.w, acc[3]);
        acc[4] = fmaf(xv, wb.x, acc[4]);
        acc[5] = fmaf(xv, wb.y, acc[5]);
        acc[6] = fmaf(xv, wb.z, acc[6]);
        acc[7] = fmaf(xv, wb.w, acc[7]);
    }

    if (cpart != 0) {
#pragma unroll
        for (int s = 0; s < 8; s++) part[cpart - 1][w][s] = acc[s];
    }
    __syncthreads();

    if (cpart == 0) {
#pragma unroll
        for (int s = 0; s < 8; s++)
            acc[s] += part[0][w][s] + part[1][w][s] + part[2][w][s]
                    + __ldg(&bias[s]);

        // pixel shuffle: out (oy=2h+r1, ox=2w+r2) uses channels s=r1*2+r2
        // (x-coord) and 4+s (y-coord). Reference quirk: x-coord uses the
        // h-linspace evaluated at oy; y-coord uses w-linspace at ox.
#pragma unroll
        for (int s = 0; s < 4; s++) {
            int oy = 2 * h + (s >> 1);
            int ox = 2 * w + (s & 1);
            float gx = fmaf((float)oy, 2.0f / 127.0f, -1.0f) + acc[s];
            float gy = fmaf((float)ox, 2.0f / 127.0f, -1.0f) + acc[4 + s];
            // ix = ((g+1)*64 - 1)*0.5 = 32*g + 31.5
            float ix = fmaf(gx, 32.0f, 31.5f);
            float iy = fmaf(gy, 32.0f, 31.5f);
            g_coord[(b * OYn + oy) * OXn + ox] = make_float2(ix, iy);
        }
    }
}

// ---------------------------------------------------------------------------
// Stage 2: bilinear sample. Block = (b, pair of channels). The two 16 KB
// planes are staged in SMEM interleaved as float2 with row pad 65, so each
// corner gather is ONE conflict-light LDS.64 serving both channels.
// Each thread processes 2 adjacent pixels (LDG.128 coord, STG.64 stores).
// ---------------------------------------------------------------------------
__device__ __forceinline__ float2 bilin2(const float2* __restrict__ plane,
                                         float ix, float iy)
{
    float fx = floorf(ix);
    float fy = floorf(iy);
    int x0 = (int)fx;
    int y0 = (int)fy;
    float wx = ix - fx;
    float wy = iy - fy;

    float w00 = (1.0f - wy) * (1.0f - wx);
    float w01 = (1.0f - wy) * wx;
    float w10 = wy * (1.0f - wx);
    float w11 = wy * wx;

    // zeros padding: zero the weight of OOB corners, clamp the index
    if ((unsigned)x0       >= (unsigned)Wn) { w00 = 0.0f; w10 = 0.0f; }
    if ((unsigned)(x0 + 1) >= (unsigned)Wn) { w01 = 0.0f; w11 = 0.0f; }
    if ((unsigned)y0       >= (unsigned)Hn) { w00 = 0.0f; w01 = 0.0f; }
    if ((unsigned)(y0 + 1) >= (unsigned)Hn) { w10 = 0.0f; w11 = 0.0f; }

    int xc0 = min(max(x0, 0), Wn - 1);
    int xc1 = min(max(x0 + 1, 0), Wn - 1);
    int yc0 = min(max(y0, 0), Hn - 1);
    int yc1 = min(max(y0 + 1, 0), Hn - 1);

    float2 v00 = plane[yc0 * PADW + xc0];
    float2 v01 = plane[yc0 * PADW + xc1];
    float2 v10 = plane[yc1 * PADW + xc0];
    float2 v11 = plane[yc1 * PADW + xc1];

    float2 r;
    r.x = fmaf(v00.x, w00, fmaf(v01.x, w01, fmaf(v10.x, w10, v11.x * w11)));
    r.y = fmaf(v00.y, w00, fmaf(v01.y, w01, fmaf(v10.y, w10, v11.y * w11)));
    return r;
}

__global__ __launch_bounds__(256) void dysample_stage2(
    const float* __restrict__ x,
    float* __restrict__ out)
{
    __shared__ float2 plane[Hn * PADW];   // 64*65*8 = 33,280 B

    int bid = blockIdx.x;                 // 0..2047
    int b   = bid >> 7;                   // batch
    int cg  = bid & 127;                  // channel pair index

    const float* p0 = x + ((size_t)b * Cn + (size_t)cg * 2) * PLANE;
    const float* p1 = p0 + PLANE;

    // Stage the two planes interleaved (float4 reads, STS.64 writes).
    for (int i = threadIdx.x * 4; i < PLANE; i += 256 * 4) {
        float4 a = *reinterpret_cast<const float4*>(p0 + i);
        float4 c = *reinterpret_cast<const float4*>(p1 + i);
        int row = i >> 6, col = i & 63;
        float2* d = &plane[row * PADW + col];
        d[0] = make_float2(a.x, c.x);
        d[1] = make_float2(a.y, c.y);
        d[2] = make_float2(a.z, c.z);
        d[3] = make_float2(a.w, c.w);
    }
    __syncthreads();

    const float* cbase = (const float*)&g_coord[(size_t)b * OYn * OXn];
    float* o0 = out + ((size_t)b * Cn + (size_t)cg * 2) * (OYn * OXn);
    float* o1 = o0 + OYn * OXn;

    // 16384 pixels, 2 per thread -> 32 iterations
#pragma unroll 2
    for (int it = 0; it < 32; ++it) {
        int p = it * 512 + threadIdx.x * 2;
        float4 co = *reinterpret_cast<const float4*>(cbase + (size_t)p * 2);

        float2 r0 = bilin2(plane, co.x, co.y);
        float2 r1 = bilin2(plane, co.z, co.w);

        *reinterpret_cast<float2*>(o0 + p) = make_float2(r0.x, r1.x);
        *reinterpret_cast<float2*>(o1 + p) = make_float2(r0.y, r1.y);
    }
}

extern "C" void kernel_launch(void* const* d_in, const int* in_sizes, int n_in,
                              void* d_out, int out_size)
{
    const float* x      = (const float*)d_in[0];
    const float* weight = (const float*)d_in[1];
    const float* bias   = (const float*)d_in[2];
    float* out          = (float*)d_out;

    dysample_stage1<<<1024, 256>>>(x, weight, bias);   // 16*64 (b,h) rows
    dysample_stage2<<<2048, 256>>>(x, out);            // 16*128 (b,ch-pair)
}